// round 12
// baseline (speedup 1.0000x reference)
#include <cuda_runtime.h>

// Problem constants
#define N_DIM   8
#define C_IN    256
#define T_DIM   512
#define V_DIM   22
#define K_TOT   7
#define S_K     3
#define C_OUTD  256

#define W_PAD     24      // w padded to 24 (pad entries are zero)
#define XM_STRIDE 26      // XM row stride (floats): conflict-free LDS.64
#define WS_STRIDE 260     // Ws row stride (floats): 16B-aligned rows, conflict-free LDS.128

// shared layout (float offsets)
#define OFF_MSP   0                       // [7][22][24]            = 3696
#define OFF_MSUM  3696                    // [7][24]                = 168
#define OFF_XMS   (3696 + 168)            // [256][26]              = 6656
#define OFF_WS    (OFF_XMS + 6656)        // [32][260]              = 8320
#define SMEM_FLOATS (OFF_WS + 8320)       // 18840 floats = 75360 B

typedef unsigned long long ull;

__device__ __forceinline__ ull bcast2(float v) {
    ull r; unsigned u = __float_as_uint(v);
    asm("mov.b64 %0, {%1, %1};" : "=l"(r) : "r"(u));
    return r;
}
__device__ __forceinline__ ull pack2(float lo, float hi) {
    ull r;
    asm("mov.b64 %0, {%1, %2};" : "=l"(r)
        : "r"(__float_as_uint(lo)), "r"(__float_as_uint(hi)));
    return r;
}
__device__ __forceinline__ void fma2(ull& d, ull a, ull b) {
    asm("fma.rn.f32x2 %0, %1, %2, %0;" : "+l"(d) : "l"(a), "l"(b));
}

__global__ __launch_bounds__(256, 2)
void sgc_fused_kernel(const float* __restrict__ x,
                      const float* __restrict__ A,
                      const float* __restrict__ attA,
                      const float* __restrict__ W,
                      const float* __restrict__ b,
                      float* __restrict__ out)
{
    extern __shared__ float sm[];
    float* Msp  = sm + OFF_MSP;    // [k][v][w_pad]
    float* Msum = sm + OFF_MSUM;   // [k][w_pad]
    float* XMs  = sm + OFF_XMS;    // [ci] stride 26
    float* Ws   = sm + OFF_WS;     // [ci_local][c] stride 260

    const int tid = threadIdx.x;
    const int bid = blockIdx.x;            // N_DIM * T_DIM = 4096
    const int n = bid >> 9;
    const int t = bid & (T_DIM - 1);

    // ---- Stage 0: mixing matrices, zero-padded to w=24 ----
    for (int idx = tid; idx < K_TOT * V_DIM * W_PAD; idx += 256) {
        int k = idx / (V_DIM * W_PAD);
        int r = idx - k * (V_DIM * W_PAD);
        int v = r / W_PAD;
        int w = r - v * W_PAD;
        float val = 0.f;
        if (w < V_DIM)
            val = (k < S_K) ? A[(k * V_DIM + v) * V_DIM + w]
                            : attA[((size_t)((n * 4 + (k - S_K)) * V_DIM + v)) * V_DIM + w];
        Msp[idx] = val;
    }
    __syncthreads();

    if (tid < K_TOT * W_PAD) {
        int k = tid / W_PAD;
        int w = tid - k * W_PAD;
        float s = 0.f;
        #pragma unroll
        for (int v = 0; v < V_DIM; v++) s += Msp[(k * V_DIM + v) * W_PAD + w];
        Msum[tid] = s;   // pad entries are zero since Msp pad is zero
    }
    __syncthreads();

    // ---- x row for this thread's ci (= tid) ----
    float xv[V_DIM];
    const float* xrow = x + (((size_t)n * C_IN + tid) * T_DIM + t) * V_DIM;
    #pragma unroll
    for (int v = 0; v < V_DIM; v++) xv[v] = xrow[v];

    // ---- output-tile mapping: 4 channels x 6 w per thread ----
    const int wg = tid & 3;            // w group 0..3
    const int cg = tid >> 2;           // c group 0..63
    const int wb = wg * 6;             // w base (0,6,12,18)
    const int cb = cg * 4;             // c base

    // ---- bias init: acc[cl][w] = sum_k b[k*256+c] * Msum[k][w] ----
    float accf[24];
    #pragma unroll
    for (int i = 0; i < 24; i++) accf[i] = 0.f;
    #pragma unroll
    for (int k = 0; k < K_TOT; k++) {
        #pragma unroll
        for (int cl = 0; cl < 4; cl++) {
            float bk = b[k * C_OUTD + cb + cl];
            #pragma unroll
            for (int jw = 0; jw < 6; jw++)
                accf[cl * 6 + jw] = fmaf(bk, Msum[k * W_PAD + wb + jw], accf[cl * 6 + jw]);
        }
    }
    ull acc2[12];
    #pragma unroll
    for (int cl = 0; cl < 4; cl++)
        #pragma unroll
        for (int j = 0; j < 3; j++)
            acc2[cl * 3 + j] = pack2(accf[cl * 6 + 2 * j], accf[cl * 6 + 2 * j + 1]);

    const int lane = tid & 31;
    const int wrp  = tid >> 5;

    for (int k = 0; k < K_TOT; k++) {
        // ---- Stage 1: XM_k[ci=tid][w] = sum_v xv[v] * M[k][v][w], packed f32x2 ----
        ull xm2[12];
        #pragma unroll
        for (int j = 0; j < 12; j++) xm2[j] = 0ull;
        #pragma unroll 2
        for (int v = 0; v < V_DIM; v++) {
            ull xvp = bcast2(xv[v]);
            const ull* mrow = (const ull*)&Msp[(k * V_DIM + v) * W_PAD];
            #pragma unroll
            for (int j = 0; j < 12; j++) fma2(xm2[j], xvp, mrow[j]);
        }
        {
            ull* xd = (ull*)&XMs[tid * XM_STRIDE];
            #pragma unroll
            for (int j = 0; j < 12; j++) xd[j] = xm2[j];
        }
        __syncthreads();

        // ---- Stage 2: acc[c][w] += sum_ci W[k*256+c][ci] * XM_k[ci][w] ----
        const float* Wk = W + (size_t)k * C_OUTD * C_IN;
        for (int chunk = 0; chunk < C_IN / 32; chunk++) {
            // cooperative transpose-load: Ws[ci_local][c] = W[c][chunk*32+ci_local]
            const float* Wg = Wk + (chunk << 5) + lane;
            #pragma unroll
            for (int rep = 0; rep < 32; rep++) {
                int c2 = rep * 8 + wrp;
                Ws[lane * WS_STRIDE + c2] = Wg[(size_t)c2 * C_IN];
            }
            __syncthreads();

            #pragma unroll 8
            for (int ci = 0; ci < 32; ci++) {
                const float4 wv = *(const float4*)&Ws[ci * WS_STRIDE + cb];
                ull w0 = bcast2(wv.x), w1 = bcast2(wv.y),
                    w2 = bcast2(wv.z), w3 = bcast2(wv.w);
                // NOTE: global input-channel index = (chunk<<5) + ci  (R2 bug fixed)
                const ull* xr = (const ull*)&XMs[(size_t)(((chunk << 5) + ci)) * XM_STRIDE + wb];
                ull x0 = xr[0], x1 = xr[1], x2 = xr[2];
                fma2(acc2[0],  w0, x0); fma2(acc2[1],  w0, x1); fma2(acc2[2],  w0, x2);
                fma2(acc2[3],  w1, x0); fma2(acc2[4],  w1, x1); fma2(acc2[5],  w1, x2);
                fma2(acc2[6],  w2, x0); fma2(acc2[7],  w2, x1); fma2(acc2[8],  w2, x2);
                fma2(acc2[9],  w3, x0); fma2(acc2[10], w3, x1); fma2(acc2[11], w3, x2);
            }
            __syncthreads();
        }
    }

    // ---- store: 4 channels, 6 (or 4 for last group) w each; 8B-aligned STG.64 ----
    #pragma unroll
    for (int cl = 0; cl < 4; cl++) {
        int c = cb + cl;
        float* orow = out + (((size_t)n * C_OUTD + c) * T_DIM + t) * V_DIM + wb;
        ull* o2 = (ull*)orow;                 // element offset is even -> 8B aligned
        o2[0] = acc2[cl * 3 + 0];
        o2[1] = acc2[cl * 3 + 1];
        if (wg < 3) o2[2] = acc2[cl * 3 + 2];  // w=22,23 are padding for wg==3
    }
}

extern "C" void kernel_launch(void* const* d_in, const int* in_sizes, int n_in,
                              void* d_out, int out_size)
{
    const float* x    = (const float*)d_in[0];
    const float* A    = (const float*)d_in[1];
    const float* attA = (const float*)d_in[2];
    const float* W    = (const float*)d_in[3];
    const float* b    = (const float*)d_in[4];
    float* out = (float*)d_out;

    const int smem_bytes = SMEM_FLOATS * 4;
    cudaFuncSetAttribute(sgc_fused_kernel,
                         cudaFuncAttributeMaxDynamicSharedMemorySize, smem_bytes);
    sgc_fused_kernel<<<N_DIM * T_DIM, 256, smem_bytes>>>(x, A, attA, W, b, out);
}

// round 16
// speedup vs baseline: 1.2373x; 1.2373x over previous
#include <cuda_runtime.h>

// Problem constants
#define N_DIM   8
#define C_IN    256
#define T_DIM   512
#define V_DIM   22
#define K_TOT   7
#define S_K     3
#define C_OUTD  256

#define W_PAD     24      // w padded to 24 (pad entries are zero)
#define XM_STRIDE 26      // XM row stride (floats)
#define WS_STRIDE 260     // Ws row stride (floats): 16B-aligned rows

// shared layout (float offsets)
#define OFF_MSP   0                         // [7][22][24]          = 3696
#define OFF_MSUM  3696                      // [7][24]              = 168
#define OFF_XMS   (3696 + 168)              // [2][256][26]         = 13312
#define OFF_WS    (OFF_XMS + 13312)         // [2][32][260]         = 16640
#define SMEM_FLOATS (OFF_WS + 16640)        // 33816 floats = 135264 B

#define XMS_SUB   (256 * XM_STRIDE)         // 6656
#define WS_BUF    (32 * WS_STRIDE)          // 8320
#define NCHUNKS   (K_TOT * 8)               // 56 total W chunks

typedef unsigned long long ull;

__device__ __forceinline__ ull bcast2(float v) {
    ull r; unsigned u = __float_as_uint(v);
    asm("mov.b64 %0, {%1, %1};" : "=l"(r) : "r"(u));
    return r;
}
__device__ __forceinline__ ull pack2(float lo, float hi) {
    ull r;
    asm("mov.b64 %0, {%1, %2};" : "=l"(r)
        : "r"(__float_as_uint(lo)), "r"(__float_as_uint(hi)));
    return r;
}
__device__ __forceinline__ void fma2(ull& d, ull a, ull b) {
    asm("fma.rn.f32x2 %0, %1, %2, %0;" : "+l"(d) : "l"(a), "l"(b));
}

__global__ __launch_bounds__(512, 1)
void sgc_fused_kernel(const float* __restrict__ x,
                      const float* __restrict__ A,
                      const float* __restrict__ attA,
                      const float* __restrict__ W,
                      const float* __restrict__ b,
                      float* __restrict__ out)
{
    extern __shared__ float sm[];
    float* Msp  = sm + OFF_MSP;    // [k][v][w_pad]
    float* Msum = sm + OFF_MSUM;   // [k][w_pad]
    float* XMs  = sm + OFF_XMS;    // [sub][ci] stride 26
    float* Ws   = sm + OFF_WS;     // [buf][ci_local][c] stride 260

    const int tid = threadIdx.x;            // 0..511
    const int bid = blockIdx.x;              // 2048 = N_DIM * T_DIM/2
    const int n  = bid >> 8;
    const int tp = bid & 255;                 // t-pair index
    const int sub = tid >> 8;                 // which t of the pair
    const int ct  = tid & 255;                // role index within sub (ci / c-w tile)
    const int t   = tp * 2 + sub;

    const int lane = tid & 31;
    const int wrp  = tid >> 5;                // 0..15

    // ---- Stage 0: mixing matrices, zero-padded to w=24 ----
    for (int idx = tid; idx < K_TOT * V_DIM * W_PAD; idx += 512) {
        int k = idx / (V_DIM * W_PAD);
        int r = idx - k * (V_DIM * W_PAD);
        int v = r / W_PAD;
        int w = r - v * W_PAD;
        float val = 0.f;
        if (w < V_DIM)
            val = (k < S_K) ? A[(k * V_DIM + v) * V_DIM + w]
                            : attA[((size_t)((n * 4 + (k - S_K)) * V_DIM + v)) * V_DIM + w];
        Msp[idx] = val;
    }
    __syncthreads();

    if (tid < K_TOT * W_PAD) {
        int k = tid / W_PAD;
        int w = tid - k * W_PAD;
        float s = 0.f;
        #pragma unroll
        for (int v = 0; v < V_DIM; v++) s += Msp[(k * V_DIM + v) * W_PAD + w];
        Msum[tid] = s;
    }

    // ---- x row for this thread's (sub, ci=ct) ----
    float xv[V_DIM];
    const float* xrow = x + (((size_t)n * C_IN + ct) * T_DIM + t) * V_DIM;
    #pragma unroll
    for (int v = 0; v < V_DIM; v++) xv[v] = xrow[v];

    // ---- output-tile mapping within sub: 4 channels x 6 w per thread ----
    const int wg = ct & 3;
    const int cg = ct >> 2;
    const int wb = wg * 6;
    const int cb = cg * 4;

    // ---- prologue: load W chunk 0 into buffer 0 ----
    // transpose mapping: lane -> ci_local, group g = rep*16 + wrp -> c rows 4g..4g+3
    {
        float pf[16];
        const float* Wg0 = W + lane;   // k=0, ch=0
        #pragma unroll
        for (int rep = 0; rep < 4; rep++) {
            int g = rep * 16 + wrp;
            #pragma unroll
            for (int j = 0; j < 4; j++)
                pf[rep * 4 + j] = Wg0[(size_t)(g * 4 + j) * C_IN];
        }
        #pragma unroll
        for (int rep = 0; rep < 4; rep++) {
            int g = rep * 16 + wrp;
            *(float4*)&Ws[lane * WS_STRIDE + g * 4] =
                make_float4(pf[rep * 4], pf[rep * 4 + 1], pf[rep * 4 + 2], pf[rep * 4 + 3]);
        }
    }
    __syncthreads();   // Msum + Ws buf0 ready

    // ---- bias init: acc[cl][w] = sum_k b[k*256+c] * Msum[k][w] ----
    float accf[24];
    #pragma unroll
    for (int i = 0; i < 24; i++) accf[i] = 0.f;
    #pragma unroll
    for (int k = 0; k < K_TOT; k++) {
        #pragma unroll
        for (int cl = 0; cl < 4; cl++) {
            float bk = b[k * C_OUTD + cb + cl];
            #pragma unroll
            for (int jw = 0; jw < 6; jw++)
                accf[cl * 6 + jw] = fmaf(bk, Msum[k * W_PAD + wb + jw], accf[cl * 6 + jw]);
        }
    }
    ull acc2[12];
    #pragma unroll
    for (int cl = 0; cl < 4; cl++)
        #pragma unroll
        for (int j = 0; j < 3; j++)
            acc2[cl * 3 + j] = pack2(accf[cl * 6 + 2 * j], accf[cl * 6 + 2 * j + 1]);

    int buf = 0;
    float* XMsub = XMs + sub * XMS_SUB;

    for (int k = 0; k < K_TOT; k++) {
        // ---- Stage 1: XM_k[sub][ci=ct][w] = sum_v xv[v] * M[k][v][w] ----
        {
            ull xm2[12];
            #pragma unroll
            for (int j = 0; j < 12; j++) xm2[j] = 0ull;
            #pragma unroll 2
            for (int v = 0; v < V_DIM; v++) {
                ull xvp = bcast2(xv[v]);
                const ull* mrow = (const ull*)&Msp[(k * V_DIM + v) * W_PAD];
                #pragma unroll
                for (int j = 0; j < 12; j++) fma2(xm2[j], xvp, mrow[j]);
            }
            ull* xd = (ull*)&XMsub[ct * XM_STRIDE];
            #pragma unroll
            for (int j = 0; j < 12; j++) xd[j] = xm2[j];
        }
        __syncthreads();

        // ---- Stage 2: 8 chunks, double-buffered W ----
        for (int ch = 0; ch < 8; ch++) {
            const int cc = k * 8 + ch;
            const bool more = (cc + 1 < NCHUNKS);

            // prefetch next chunk's W slice into registers (overlaps compute)
            float pf[16];
            if (more) {
                const int nk  = (cc + 1) >> 3;
                const int nch = (cc + 1) & 7;
                const float* Wg = W + (size_t)nk * C_OUTD * C_IN + (nch << 5) + lane;
                #pragma unroll
                for (int rep = 0; rep < 4; rep++) {
                    int g = rep * 16 + wrp;
                    #pragma unroll
                    for (int j = 0; j < 4; j++)
                        pf[rep * 4 + j] = Wg[(size_t)(g * 4 + j) * C_IN];
                }
            }

            const float* Wsb = Ws + buf * WS_BUF;
            #pragma unroll 8
            for (int ci = 0; ci < 32; ci++) {
                const float4 wv = *(const float4*)&Wsb[ci * WS_STRIDE + cb];
                ull w0 = bcast2(wv.x), w1 = bcast2(wv.y),
                    w2 = bcast2(wv.z), w3 = bcast2(wv.w);
                const ull* xr = (const ull*)&XMsub[(size_t)(((ch << 5) + ci)) * XM_STRIDE + wb];
                ull x0 = xr[0], x1 = xr[1], x2 = xr[2];
                fma2(acc2[0],  w0, x0); fma2(acc2[1],  w0, x1); fma2(acc2[2],  w0, x2);
                fma2(acc2[3],  w1, x0); fma2(acc2[4],  w1, x1); fma2(acc2[5],  w1, x2);
                fma2(acc2[6],  w2, x0); fma2(acc2[7],  w2, x1); fma2(acc2[8],  w2, x2);
                fma2(acc2[9],  w3, x0); fma2(acc2[10], w3, x1); fma2(acc2[11], w3, x2);
            }

            // store prefetched chunk into the other buffer (conflict-free STS.128)
            if (more) {
                float* Wsn = Ws + (buf ^ 1) * WS_BUF;
                #pragma unroll
                for (int rep = 0; rep < 4; rep++) {
                    int g = rep * 16 + wrp;
                    *(float4*)&Wsn[lane * WS_STRIDE + g * 4] =
                        make_float4(pf[rep * 4], pf[rep * 4 + 1],
                                    pf[rep * 4 + 2], pf[rep * 4 + 3]);
                }
            }
            __syncthreads();
            buf ^= 1;
        }
        // after chunk-7 sync, XMs is free to overwrite and next buf is loaded
    }

    // ---- store: 4 channels, 6 (or 4 for last group) w each ----
    #pragma unroll
    for (int cl = 0; cl < 4; cl++) {
        int c = cb + cl;
        float* orow = out + (((size_t)n * C_OUTD + c) * T_DIM + t) * V_DIM + wb;
        ull* o2 = (ull*)orow;
        o2[0] = acc2[cl * 3 + 0];
        o2[1] = acc2[cl * 3 + 1];
        if (wg < 3) o2[2] = acc2[cl * 3 + 2];
    }
}

extern "C" void kernel_launch(void* const* d_in, const int* in_sizes, int n_in,
                              void* d_out, int out_size)
{
    const float* x    = (const float*)d_in[0];
    const float* A    = (const float*)d_in[1];
    const float* attA = (const float*)d_in[2];
    const float* W    = (const float*)d_in[3];
    const float* b    = (const float*)d_in[4];
    float* out = (float*)d_out;

    const int smem_bytes = SMEM_FLOATS * 4;
    cudaFuncSetAttribute(sgc_fused_kernel,
                         cudaFuncAttributeMaxDynamicSharedMemorySize, smem_bytes);
    sgc_fused_kernel<<<N_DIM * (T_DIM / 2), 512, smem_bytes>>>(x, A, attA, W, b, out);
}